// round 2
// baseline (speedup 1.0000x reference)
#include <cuda_runtime.h>
#include <math.h>

#define D_   1024
#define T_   256
#define B_   8
#define M_   (B_*T_)        // 2048 rows (b,t)
#define HMHA 16
#define DH   64
#define HGAT 8
#define GDH  128
#define KW   7
#define K5D  (5*D_)
#define KCONV (KW*D_)       // 7168

// ---------------- scratch (device globals; no allocation) ----------------
__device__ float g_ms[M_ * K5D];            // (2048, 5120) concat conv outputs
__device__ float g_z [M_ * D_];             // post fusion-proj / LN / GELU
__device__ float g_q [M_ * D_];
__device__ float g_k [M_ * D_];
__device__ float g_v [M_ * D_];
__device__ float g_s [B_*HMHA * T_ * T_];   // attention scores (128, 256, 256)
__device__ float g_ctx[M_ * D_];
__device__ float g_att[M_ * D_];
__device__ float g_hg [M_ * D_];
__device__ float g_e1[M_ * HGAT];
__device__ float g_e2[M_ * HGAT];
__device__ float g_m2[HGAT];

// =====================================================================
// Generic tiled GEMM: C[m,n] = sum_k A[m*lda+k] * W[n*ldw+k] + bias[n]
// BM=BN=64, BK=16, 256 threads, 4x4 micro-tile.
// =====================================================================
__global__ __launch_bounds__(256)
void gemm_wT_kernel(const float* __restrict__ A, const float* __restrict__ W,
                    const float* __restrict__ bias, float* __restrict__ C,
                    int K, int lda, int ldw, int ldc)
{
    __shared__ __align__(16) float As[16][68];
    __shared__ __align__(16) float Bs[16][68];
    const int bm = blockIdx.y * 64;
    const int bn = blockIdx.x * 64;
    const int tid = threadIdx.x;
    const int lk = tid & 15, lr = tid >> 4;
    const int tx = tid & 15, ty = tid >> 4;
    float acc[4][4] = {};
    for (int k0 = 0; k0 < K; k0 += 16) {
        #pragma unroll
        for (int p = 0; p < 4; p++) {
            int m = bm + lr + 16*p;
            As[lk][lr + 16*p] = A[(size_t)m * lda + k0 + lk];
        }
        #pragma unroll
        for (int p = 0; p < 4; p++) {
            int n = bn + lr + 16*p;
            Bs[lk][lr + 16*p] = W[(size_t)n * ldw + k0 + lk];
        }
        __syncthreads();
        #pragma unroll
        for (int k = 0; k < 16; k++) {
            float a[4], b[4];
            *(float4*)a = *(const float4*)&As[k][ty*4];
            *(float4*)b = *(const float4*)&Bs[k][tx*4];
            #pragma unroll
            for (int i = 0; i < 4; i++)
                #pragma unroll
                for (int j = 0; j < 4; j++)
                    acc[i][j] += a[i] * b[j];
        }
        __syncthreads();
    }
    #pragma unroll
    for (int i = 0; i < 4; i++) {
        int m = bm + ty*4 + i;
        #pragma unroll
        for (int j = 0; j < 4; j++) {
            int n = bn + tx*4 + j;
            C[(size_t)m * ldc + n] = acc[i][j] + bias[n];
        }
    }
}

// =====================================================================
// Dilated conv as implicit GEMM:
// ms[m, ccol+o] = sum_{kk in 7*1024} x[b, t+(tap-3)*dil, i] * w[o,i,tap] + b[o]
// =====================================================================
__global__ __launch_bounds__(256)
void conv_gemm_kernel(const float* __restrict__ feat, const float* __restrict__ w,
                      const float* __restrict__ bias, float* __restrict__ out,
                      int dil, int ccol)
{
    __shared__ __align__(16) float As[16][68];
    __shared__ __align__(16) float Bs[16][68];
    const int bm = blockIdx.y * 64;
    const int bn = blockIdx.x * 64;
    const int tid = threadIdx.x;
    const int lk = tid & 15, lr = tid >> 4;
    const int tx = tid & 15, ty = tid >> 4;
    float acc[4][4] = {};
    for (int k0 = 0; k0 < KCONV; k0 += 16) {
        int kk = k0 + lk;
        int tap = kk >> 10;
        int ci  = kk & 1023;
        int off = (tap - 3) * dil;
        #pragma unroll
        for (int p = 0; p < 4; p++) {
            int m = bm + lr + 16*p;
            int b = m >> 8, t = m & 255;
            int tt = t + off;
            float v = 0.f;
            if (tt >= 0 && tt < T_)
                v = feat[((size_t)(b * T_ + tt)) * D_ + ci];
            As[lk][lr + 16*p] = v;
        }
        #pragma unroll
        for (int p = 0; p < 4; p++) {
            int n = bn + lr + 16*p;
            Bs[lk][lr + 16*p] = w[(size_t)n * KCONV + ci * 7 + tap];
        }
        __syncthreads();
        #pragma unroll
        for (int k = 0; k < 16; k++) {
            float a[4], b[4];
            *(float4*)a = *(const float4*)&As[k][ty*4];
            *(float4*)b = *(const float4*)&Bs[k][tx*4];
            #pragma unroll
            for (int i = 0; i < 4; i++)
                #pragma unroll
                for (int j = 0; j < 4; j++)
                    acc[i][j] += a[i] * b[j];
        }
        __syncthreads();
    }
    #pragma unroll
    for (int i = 0; i < 4; i++) {
        int m = bm + ty*4 + i;
        #pragma unroll
        for (int j = 0; j < 4; j++) {
            int n = bn + tx*4 + j;
            out[(size_t)m * K5D + ccol + n] = acc[i][j] + bias[n];
        }
    }
}

// =====================================================================
// LayerNorm + exact GELU, in place on (2048, 1024). One block per row.
// =====================================================================
__global__ __launch_bounds__(256)
void ln_gelu_kernel(float* __restrict__ z, const float* __restrict__ g,
                    const float* __restrict__ b)
{
    const int row = blockIdx.x;
    const int tid = threadIdx.x;
    float* p = z + (size_t)row * D_;
    float4 v = ((const float4*)p)[tid];
    float s  = v.x + v.y + v.z + v.w;
    float ss = v.x*v.x + v.y*v.y + v.z*v.z + v.w*v.w;
    #pragma unroll
    for (int o = 16; o; o >>= 1) {
        s  += __shfl_xor_sync(0xffffffffu, s,  o);
        ss += __shfl_xor_sync(0xffffffffu, ss, o);
    }
    __shared__ float ws[8], wss[8];
    __shared__ float mu_s, inv_s;
    int lane = tid & 31, wid = tid >> 5;
    if (lane == 0) { ws[wid] = s; wss[wid] = ss; }
    __syncthreads();
    if (tid == 0) {
        float S = 0.f, SS = 0.f;
        #pragma unroll
        for (int i = 0; i < 8; i++) { S += ws[i]; SS += wss[i]; }
        float mu = S * (1.f / D_);
        float var = SS * (1.f / D_) - mu * mu;
        mu_s = mu;
        inv_s = rsqrtf(var + 1e-5f);
    }
    __syncthreads();
    float mu = mu_s, inv = inv_s;
    float4 gg = ((const float4*)g)[tid];
    float4 bb = ((const float4*)b)[tid];
    float y[4] = { (v.x-mu)*inv*gg.x + bb.x, (v.y-mu)*inv*gg.y + bb.y,
                   (v.z-mu)*inv*gg.z + bb.z, (v.w-mu)*inv*gg.w + bb.w };
    float4 o;
    o.x = 0.5f*y[0]*(1.f + erff(y[0]*0.70710678118654752f));
    o.y = 0.5f*y[1]*(1.f + erff(y[1]*0.70710678118654752f));
    o.z = 0.5f*y[2]*(1.f + erff(y[2]*0.70710678118654752f));
    o.w = 0.5f*y[3]*(1.f + erff(y[3]*0.70710678118654752f));
    ((float4*)p)[tid] = o;
}

// =====================================================================
// Attention scores: S[bh, m, n] = 0.125 * sum_d q[b,m,h,d] k[b,n,h,d]
// =====================================================================
__global__ __launch_bounds__(256)
void attn_scores_kernel(const float* __restrict__ q, const float* __restrict__ kmat,
                        float* __restrict__ s)
{
    const int bh = blockIdx.z;
    const int b = bh >> 4, h = bh & 15;
    const int bm = blockIdx.y * 64, bn = blockIdx.x * 64;
    __shared__ __align__(16) float As[16][68];
    __shared__ __align__(16) float Bs[16][68];
    const int tid = threadIdx.x;
    const int lk = tid & 15, lr = tid >> 4;
    const int tx = tid & 15, ty = tid >> 4;
    float acc[4][4] = {};
    for (int k0 = 0; k0 < DH; k0 += 16) {
        #pragma unroll
        for (int p = 0; p < 4; p++) {
            int m = bm + lr + 16*p;
            As[lk][lr+16*p] = q[((size_t)(b*T_ + m))*D_ + h*DH + k0 + lk];
        }
        #pragma unroll
        for (int p = 0; p < 4; p++) {
            int n = bn + lr + 16*p;
            Bs[lk][lr+16*p] = kmat[((size_t)(b*T_ + n))*D_ + h*DH + k0 + lk];
        }
        __syncthreads();
        #pragma unroll
        for (int k = 0; k < 16; k++) {
            float a[4], bb[4];
            *(float4*)a  = *(const float4*)&As[k][ty*4];
            *(float4*)bb = *(const float4*)&Bs[k][tx*4];
            #pragma unroll
            for (int i = 0; i < 4; i++)
                #pragma unroll
                for (int j = 0; j < 4; j++)
                    acc[i][j] += a[i]*bb[j];
        }
        __syncthreads();
    }
    #pragma unroll
    for (int i = 0; i < 4; i++) {
        int m = bm + ty*4 + i;
        #pragma unroll
        for (int j = 0; j < 4; j++) {
            int n = bn + tx*4 + j;
            s[((size_t)bh*T_ + m)*T_ + n] = acc[i][j] * 0.125f;
        }
    }
}

// Row softmax over 256 entries. One warp per row.
__global__ __launch_bounds__(256)
void softmax_kernel(float* __restrict__ s)
{
    int row  = (blockIdx.x * blockDim.x + threadIdx.x) >> 5;
    int lane = threadIdx.x & 31;
    float* p = s + (size_t)row * T_;
    float v[8];
    float m = -1e30f;
    #pragma unroll
    for (int r = 0; r < 8; r++) { v[r] = p[lane + 32*r]; m = fmaxf(m, v[r]); }
    #pragma unroll
    for (int o = 16; o; o >>= 1) m = fmaxf(m, __shfl_xor_sync(0xffffffffu, m, o));
    float sum = 0.f;
    #pragma unroll
    for (int r = 0; r < 8; r++) { v[r] = __expf(v[r] - m); sum += v[r]; }
    #pragma unroll
    for (int o = 16; o; o >>= 1) sum += __shfl_xor_sync(0xffffffffu, sum, o);
    float inv = 1.f / sum;
    #pragma unroll
    for (int r = 0; r < 8; r++) p[lane + 32*r] = v[r] * inv;
}

// ctx[b,m,h,d] = sum_k P[bh,m,k] v[b,k,h,d]   (BN = 64 = full head dim)
__global__ __launch_bounds__(256)
void attn_ctx_kernel(const float* __restrict__ s, const float* __restrict__ v,
                     float* __restrict__ ctx)
{
    const int bh = blockIdx.z;
    const int b = bh >> 4, h = bh & 15;
    const int bm = blockIdx.y * 64;
    __shared__ __align__(16) float As[16][68];
    __shared__ __align__(16) float Bs[16][68];
    const int tid = threadIdx.x;
    const int lk = tid & 15, lr = tid >> 4;
    const int bn_ = tid & 63, bkk = tid >> 6;
    const int tx = tid & 15, ty = tid >> 4;
    float acc[4][4] = {};
    for (int k0 = 0; k0 < T_; k0 += 16) {
        #pragma unroll
        for (int p = 0; p < 4; p++) {
            int m = bm + lr + 16*p;
            As[lk][lr+16*p] = s[((size_t)bh*T_ + m)*T_ + k0 + lk];
        }
        #pragma unroll
        for (int p = 0; p < 4; p++) {
            int jj = bkk + 4*p;
            Bs[jj][bn_] = v[((size_t)(b*T_ + k0 + jj))*D_ + h*DH + bn_];
        }
        __syncthreads();
        #pragma unroll
        for (int k = 0; k < 16; k++) {
            float a[4], bb[4];
            *(float4*)a  = *(const float4*)&As[k][ty*4];
            *(float4*)bb = *(const float4*)&Bs[k][tx*4];
            #pragma unroll
            for (int i = 0; i < 4; i++)
                #pragma unroll
                for (int j = 0; j < 4; j++)
                    acc[i][j] += a[i]*bb[j];
        }
        __syncthreads();
    }
    #pragma unroll
    for (int i = 0; i < 4; i++) {
        int m = bm + ty*4 + i;
        #pragma unroll
        for (int j = 0; j < 4; j++)
            ctx[((size_t)(b*T_ + m))*D_ + h*DH + tx*4 + j] = acc[i][j];
    }
}

// =====================================================================
// GAT: e1/e2 per (node, head); one warp each.
// =====================================================================
__global__ __launch_bounds__(256)
void e12_kernel(const float* __restrict__ hg, const float* __restrict__ a1,
                const float* __restrict__ a2, float* __restrict__ e1,
                float* __restrict__ e2)
{
    int wid  = (blockIdx.x * blockDim.x + threadIdx.x) >> 5;
    int lane = threadIdx.x & 31;
    int n = wid >> 3, h = wid & 7;
    const float* row = hg + (size_t)n * D_ + h * GDH;
    float s1 = 0.f, s2 = 0.f;
    #pragma unroll
    for (int r = 0; r < 4; r++) {
        float x = row[lane + 32*r];
        s1 += x * a1[lane + 32*r];
        s2 += x * a2[lane + 32*r];
    }
    #pragma unroll
    for (int o = 16; o; o >>= 1) {
        s1 += __shfl_xor_sync(0xffffffffu, s1, o);
        s2 += __shfl_xor_sync(0xffffffffu, s2, o);
    }
    if (lane == 0) { e1[n*HGAT + h] = s1; e2[n*HGAT + h] = s2; }
}

__global__ __launch_bounds__(256)
void e2max_kernel(const float* __restrict__ e2, float* __restrict__ m2)
{
    int h = blockIdx.x, tid = threadIdx.x;
    float m = -1e30f;
    for (int n = tid; n < M_; n += 256) m = fmaxf(m, e2[n*HGAT + h]);
    __shared__ float sm[256];
    sm[tid] = m; __syncthreads();
    for (int s = 128; s > 0; s >>= 1) {
        if (tid < s) sm[tid] = fmaxf(sm[tid], sm[tid + s]);
        __syncthreads();
    }
    if (tid == 0) m2[h] = sm[0];
}

// =====================================================================
// GAT aggregation GEMM with on-the-fly alpha, fused denom + ELU + residual.
// Block: (head h, 64-row tile) -> 64 x 128 output. 256 thr, 4x8 micro.
// =====================================================================
__global__ __launch_bounds__(256)
void gat_gemm_kernel(const float* __restrict__ hg, const float* __restrict__ e1,
                     const float* __restrict__ e2, const float* __restrict__ m2,
                     const float* __restrict__ feat, float* __restrict__ out)
{
    const int h  = blockIdx.x;
    const int bm = blockIdx.y * 64;
    __shared__ __align__(16) float As[16][68];
    __shared__ __align__(16) float Bs[16][136];
    __shared__ float se1[64], smrow[64];
    const int tid = threadIdx.x;
    if (tid < 64) {
        float v1 = e1[(bm + tid)*HGAT + h];
        float s = v1 + m2[h];
        smrow[tid] = s > 0.f ? s : 0.2f * s;
        se1[tid] = v1;
    }
    __syncthreads();
    const int lk = tid & 15, lr = tid >> 4;
    const int bd = tid & 127, bj = tid >> 7;
    const int tx = tid & 15, ty = tid >> 4;
    float acc[4][8] = {};
    float dacc[4] = {};
    for (int k0 = 0; k0 < M_; k0 += 16) {
        float e2v = e2[(k0 + lk)*HGAT + h];
        #pragma unroll
        for (int p = 0; p < 4; p++) {
            int i = lr + 16*p;
            float s = se1[i] + e2v;
            float l = s > 0.f ? s : 0.2f * s;
            As[lk][i] = __expf(l - smrow[i]);
        }
        #pragma unroll
        for (int p = 0; p < 8; p++) {
            int jj = bj + 2*p;
            Bs[jj][bd] = hg[(size_t)(k0 + jj)*D_ + h*GDH + bd];
        }
        __syncthreads();
        #pragma unroll
        for (int k = 0; k < 16; k++) {
            float a[4], b[8];
            *(float4*)a      = *(const float4*)&As[k][ty*4];
            *(float4*)&b[0]  = *(const float4*)&Bs[k][tx*8];
            *(float4*)&b[4]  = *(const float4*)&Bs[k][tx*8 + 4];
            #pragma unroll
            for (int i = 0; i < 4; i++) {
                dacc[i] += a[i];
                #pragma unroll
                for (int j = 0; j < 8; j++)
                    acc[i][j] += a[i]*b[j];
            }
        }
        __syncthreads();
    }
    #pragma unroll
    for (int i = 0; i < 4; i++) {
        int m = bm + ty*4 + i;
        float inv = 1.f / dacc[i];
        #pragma unroll
        for (int j = 0; j < 8; j++) {
            float v = acc[i][j] * inv;
            v = v > 0.f ? v : expm1f(v);                 // ELU
            int col = h*GDH + tx*8 + j;
            out[(size_t)m*D_ + col] = v + feat[(size_t)m*D_ + col];
        }
    }
}

// =====================================================================
extern "C" void kernel_launch(void* const* d_in, const int* in_sizes, int n_in,
                              void* d_out, int out_size)
{
    const float* feat = (const float*)d_in[0];

    // Bind conv weights/biases by SIZE, tolerating both interleaved
    // (w0,b0,w1,b1,...) and grouped (w0..w4,b0..b4) metadata orders.
    const float* cw[5];
    const float* cb[5];
    int wi = 0, bi = 0;
    for (int i = 1; i <= 10; i++) {
        if (in_sizes[i] == D_ * D_ * KW) { if (wi < 5) cw[wi++] = (const float*)d_in[i]; }
        else                             { if (bi < 5) cb[bi++] = (const float*)d_in[i]; }
    }

    const float* fp_w = (const float*)d_in[11];
    const float* fp_b = (const float*)d_in[12];
    const float* ln_g = (const float*)d_in[13];
    const float* ln_b = (const float*)d_in[14];
    const float* wq = (const float*)d_in[15];
    const float* bq = (const float*)d_in[16];
    const float* wk = (const float*)d_in[17];
    const float* bk = (const float*)d_in[18];
    const float* wv = (const float*)d_in[19];
    const float* bv = (const float*)d_in[20];
    const float* wo = (const float*)d_in[21];
    const float* bo = (const float*)d_in[22];
    const float* gat_w = (const float*)d_in[23];
    const float* gat_b = (const float*)d_in[24];
    const float* a1 = (const float*)d_in[25];
    const float* a2 = (const float*)d_in[26];
    float* out = (float*)d_out;

    float *ms, *z, *q, *k, *v, *s, *ctx, *att, *hg, *e1, *e2, *m2;
    cudaGetSymbolAddress((void**)&ms,  g_ms);
    cudaGetSymbolAddress((void**)&z,   g_z);
    cudaGetSymbolAddress((void**)&q,   g_q);
    cudaGetSymbolAddress((void**)&k,   g_k);
    cudaGetSymbolAddress((void**)&v,   g_v);
    cudaGetSymbolAddress((void**)&s,   g_s);
    cudaGetSymbolAddress((void**)&ctx, g_ctx);
    cudaGetSymbolAddress((void**)&att, g_att);
    cudaGetSymbolAddress((void**)&hg,  g_hg);
    cudaGetSymbolAddress((void**)&e1,  g_e1);
    cudaGetSymbolAddress((void**)&e2,  g_e2);
    cudaGetSymbolAddress((void**)&m2,  g_m2);

    const int dil[5] = {1, 2, 4, 8, 16};

    // 1) dilated convs -> g_ms (2048, 5120)
    for (int c = 0; c < 5; c++)
        conv_gemm_kernel<<<dim3(16, 32), 256>>>(feat, cw[c], cb[c], ms, dil[c], c*D_);

    // 2) fusion projection (K=5120) -> g_z, then LN+GELU in place
    gemm_wT_kernel<<<dim3(16, 32), 256>>>(ms, fp_w, fp_b, z, K5D, K5D, K5D, D_);
    ln_gelu_kernel<<<M_, 256>>>(z, ln_g, ln_b);

    // 3) q, k, v projections
    gemm_wT_kernel<<<dim3(16, 32), 256>>>(z, wq, bq, q, D_, D_, D_, D_);
    gemm_wT_kernel<<<dim3(16, 32), 256>>>(z, wk, bk, k, D_, D_, D_, D_);
    gemm_wT_kernel<<<dim3(16, 32), 256>>>(z, wv, bv, v, D_, D_, D_, D_);

    // 4) attention
    attn_scores_kernel<<<dim3(4, 4, B_*HMHA), 256>>>(q, k, s);
    softmax_kernel<<<(B_*HMHA*T_)/8, 256>>>(s);
    attn_ctx_kernel<<<dim3(1, 4, B_*HMHA), 256>>>(s, v, ctx);

    // 5) output projection, GAT projection
    gemm_wT_kernel<<<dim3(16, 32), 256>>>(ctx, wo, bo, att, D_, D_, D_, D_);
    gemm_wT_kernel<<<dim3(16, 32), 256>>>(att, gat_w, gat_b, hg, D_, D_, D_, D_);

    // 6) GAT attention logits + stable max
    e12_kernel<<<(M_*HGAT)/8, 256>>>(hg, a1, a2, e1, e2);
    e2max_kernel<<<HGAT, 256>>>(e2, m2);

    // 7) GAT aggregation + ELU + residual -> d_out
    gat_gemm_kernel<<<dim3(HGAT, 32), 256>>>(hg, e1, e2, m2, feat, out);
}

// round 3
// speedup vs baseline: 1.2387x; 1.2387x over previous
#include <cuda_runtime.h>
#include <math.h>

#define D_   1024
#define T_   256
#define B_   8
#define M_   (B_*T_)        // 2048 rows (b,t)
#define HMHA 16
#define DH   64
#define HGAT 8
#define GDH  128
#define KW   7
#define K5D  (5*D_)
#define KCONV (KW*D_)       // 7168

// ---------------- scratch (device globals; no allocation) ----------------
__device__ float g_wt[5 * KW * D_ * D_];    // transformed conv weights [c][tap][o][ci]
__device__ float g_ms[M_ * K5D];            // (2048, 5120) concat conv outputs
__device__ float g_z [M_ * D_];             // post fusion-proj / LN / GELU
__device__ float g_q [M_ * D_];
__device__ float g_k [M_ * D_];
__device__ float g_v [M_ * D_];
__device__ float g_s [B_*HMHA * T_ * T_];   // attention scores (128, 256, 256)
__device__ float g_ctx[M_ * D_];
__device__ float g_att[M_ * D_];
__device__ float g_hg [M_ * D_];
__device__ float g_e1[M_ * HGAT];
__device__ float g_e2[M_ * HGAT];
__device__ float g_m2[HGAT];

// =====================================================================
// Weight transform: wt[tap][o][ci] = w[o*7168 + ci*7 + tap]
// =====================================================================
__global__ __launch_bounds__(256)
void wtrans_kernel(const float* __restrict__ w, float* __restrict__ wt)
{
    int idx = blockIdx.x * 256 + threadIdx.x;      // over 7*1024*1024
    int tap = idx >> 20;
    int rem = idx & ((1 << 20) - 1);
    int o  = rem >> 10;
    int ci = rem & 1023;
    wt[idx] = __ldg(&w[(size_t)o * KCONV + ci * 7 + tap]);
}

// =====================================================================
// 128x128x16 double-buffered fp32 GEMM, 256 threads, 8x8 microtile.
// C[m,n] = sum_k A[m*lda+k] * W[n*ldw+k] + bias[n]
// =====================================================================
#define GL_A(p, k0) ra[p] = *(const float4*)&A[(size_t)(bm + ar + 64*(p))*lda + (k0) + ac]
#define GL_B(p, k0) rb[p] = *(const float4*)&W[(size_t)(bn + ar + 64*(p))*ldw + (k0) + ac]
#define SST(buf) do { \
    _Pragma("unroll") \
    for (int p = 0; p < 2; p++) { \
        int mm = ar + 64*p; \
        As[buf][ac+0][mm] = ra[p].x; As[buf][ac+1][mm] = ra[p].y; \
        As[buf][ac+2][mm] = ra[p].z; As[buf][ac+3][mm] = ra[p].w; \
        Bs[buf][ac+0][mm] = rb[p].x; Bs[buf][ac+1][mm] = rb[p].y; \
        Bs[buf][ac+2][mm] = rb[p].z; Bs[buf][ac+3][mm] = rb[p].w; \
    } } while (0)
#define COMPUTE(buf) do { \
    _Pragma("unroll") \
    for (int k = 0; k < 16; k++) { \
        float a[8], b[8]; \
        *(float4*)&a[0] = *(const float4*)&As[buf][k][ty*8]; \
        *(float4*)&a[4] = *(const float4*)&As[buf][k][ty*8+4]; \
        *(float4*)&b[0] = *(const float4*)&Bs[buf][k][tx*8]; \
        *(float4*)&b[4] = *(const float4*)&Bs[buf][k][tx*8+4]; \
        _Pragma("unroll") \
        for (int i = 0; i < 8; i++) \
            _Pragma("unroll") \
            for (int j = 0; j < 8; j++) \
                acc[i][j] += a[i]*b[j]; \
    } } while (0)

__global__ __launch_bounds__(256)
void gemm128_wT(const float* __restrict__ A, const float* __restrict__ W,
                const float* __restrict__ bias, float* __restrict__ C,
                int K, int lda, int ldw, int ldc)
{
    __shared__ __align__(16) float As[2][16][132];
    __shared__ __align__(16) float Bs[2][16][132];
    const int bm = blockIdx.y * 128, bn = blockIdx.x * 128;
    const int tid = threadIdx.x;
    const int ar = tid >> 2, ac = (tid & 3) << 2;
    const int tx = tid & 15, ty = tid >> 4;
    float4 ra[2], rb[2];
    float acc[8][8] = {};

    GL_A(0, 0); GL_A(1, 0); GL_B(0, 0); GL_B(1, 0);
    SST(0);
    __syncthreads();
    const int nk = K >> 4;
    for (int kb = 0; kb < nk; kb++) {
        if (kb + 1 < nk) {
            int k0 = (kb + 1) << 4;
            GL_A(0, k0); GL_A(1, k0); GL_B(0, k0); GL_B(1, k0);
        }
        int buf = kb & 1;
        COMPUTE(buf);
        if (kb + 1 < nk) SST(buf ^ 1);
        __syncthreads();
    }
    #pragma unroll
    for (int i = 0; i < 8; i++) {
        int m = bm + ty*8 + i;
        #pragma unroll
        for (int j = 0; j < 8; j += 4) {
            int n = bn + tx*8 + j;
            float4 o;
            o.x = acc[i][j+0] + bias[n+0];
            o.y = acc[i][j+1] + bias[n+1];
            o.z = acc[i][j+2] + bias[n+2];
            o.w = acc[i][j+3] + bias[n+3];
            *(float4*)&C[(size_t)m*ldc + n] = o;
        }
    }
}

// =====================================================================
// Conv as implicit GEMM, 128x128x16 double-buffered, weights pre-transformed.
// out[m, ccol+o] = sum_{tap,ci} feat[b, t+(tap-3)*dil, ci] * wt[tap][o][ci] + b[o]
// =====================================================================
#define GL_CA(p, tap, ci, off) do { \
    int mm = bm + ar + 64*(p); \
    int bb = mm >> 8, tt = (mm & 255) + (off); \
    if (tt >= 0 && tt < T_) \
        ra[p] = *(const float4*)&feat[((size_t)(bb * T_ + tt))*D_ + (ci)]; \
    else ra[p] = make_float4(0.f, 0.f, 0.f, 0.f); \
    } while (0)
#define GL_CB(p, tap, ci) rb[p] = *(const float4*)&wt[(size_t)(tap)*D_*D_ + (size_t)(bn + ar + 64*(p))*D_ + (ci)]

__global__ __launch_bounds__(256)
void conv128_kernel(const float* __restrict__ feat, const float* __restrict__ wt,
                    const float* __restrict__ bias, float* __restrict__ out,
                    int dil, int ccol)
{
    __shared__ __align__(16) float As[2][16][132];
    __shared__ __align__(16) float Bs[2][16][132];
    const int bm = blockIdx.y * 128, bn = blockIdx.x * 128;
    const int tid = threadIdx.x;
    const int ar = tid >> 2, ac = (tid & 3) << 2;
    const int tx = tid & 15, ty = tid >> 4;
    float4 ra[2], rb[2];
    float acc[8][8] = {};

    {
        int kk = ac;                      // k0 = 0
        int tap = 0, ci = kk, off = -3 * dil;
        GL_CA(0, tap, ci, off); GL_CA(1, tap, ci, off);
        GL_CB(0, tap, ci);      GL_CB(1, tap, ci);
    }
    SST(0);
    __syncthreads();
    const int nk = KCONV >> 4;            // 448
    for (int kb = 0; kb < nk; kb++) {
        if (kb + 1 < nk) {
            int kk = ((kb + 1) << 4) + ac;
            int tap = kk >> 10, ci = kk & 1023;
            int off = (tap - 3) * dil;
            GL_CA(0, tap, ci, off); GL_CA(1, tap, ci, off);
            GL_CB(0, tap, ci);      GL_CB(1, tap, ci);
        }
        int buf = kb & 1;
        COMPUTE(buf);
        if (kb + 1 < nk) SST(buf ^ 1);
        __syncthreads();
    }
    #pragma unroll
    for (int i = 0; i < 8; i++) {
        int m = bm + ty*8 + i;
        #pragma unroll
        for (int j = 0; j < 8; j += 4) {
            int n = bn + tx*8 + j;
            float4 o;
            o.x = acc[i][j+0] + bias[n+0];
            o.y = acc[i][j+1] + bias[n+1];
            o.z = acc[i][j+2] + bias[n+2];
            o.w = acc[i][j+3] + bias[n+3];
            *(float4*)&out[(size_t)m*K5D + ccol + n] = o;
        }
    }
}

// =====================================================================
// LayerNorm + exact GELU, in place on (2048, 1024). One block per row.
// =====================================================================
__global__ __launch_bounds__(256)
void ln_gelu_kernel(float* __restrict__ z, const float* __restrict__ g,
                    const float* __restrict__ b)
{
    const int row = blockIdx.x;
    const int tid = threadIdx.x;
    float* p = z + (size_t)row * D_;
    float4 v = ((const float4*)p)[tid];
    float s  = v.x + v.y + v.z + v.w;
    float ss = v.x*v.x + v.y*v.y + v.z*v.z + v.w*v.w;
    #pragma unroll
    for (int o = 16; o; o >>= 1) {
        s  += __shfl_xor_sync(0xffffffffu, s,  o);
        ss += __shfl_xor_sync(0xffffffffu, ss, o);
    }
    __shared__ float ws[8], wss[8];
    __shared__ float mu_s, inv_s;
    int lane = tid & 31, wid = tid >> 5;
    if (lane == 0) { ws[wid] = s; wss[wid] = ss; }
    __syncthreads();
    if (tid == 0) {
        float S = 0.f, SS = 0.f;
        #pragma unroll
        for (int i = 0; i < 8; i++) { S += ws[i]; SS += wss[i]; }
        float mu = S * (1.f / D_);
        float var = SS * (1.f / D_) - mu * mu;
        mu_s = mu;
        inv_s = rsqrtf(var + 1e-5f);
    }
    __syncthreads();
    float mu = mu_s, inv = inv_s;
    float4 gg = ((const float4*)g)[tid];
    float4 bb = ((const float4*)b)[tid];
    float y[4] = { (v.x-mu)*inv*gg.x + bb.x, (v.y-mu)*inv*gg.y + bb.y,
                   (v.z-mu)*inv*gg.z + bb.z, (v.w-mu)*inv*gg.w + bb.w };
    float4 o;
    o.x = 0.5f*y[0]*(1.f + erff(y[0]*0.70710678118654752f));
    o.y = 0.5f*y[1]*(1.f + erff(y[1]*0.70710678118654752f));
    o.z = 0.5f*y[2]*(1.f + erff(y[2]*0.70710678118654752f));
    o.w = 0.5f*y[3]*(1.f + erff(y[3]*0.70710678118654752f));
    ((float4*)p)[tid] = o;
}

// =====================================================================
// Attention scores: S[bh, m, n] = 0.125 * sum_d q[b,m,h,d] k[b,n,h,d]
// =====================================================================
__global__ __launch_bounds__(256)
void attn_scores_kernel(const float* __restrict__ q, const float* __restrict__ kmat,
                        float* __restrict__ s)
{
    const int bh = blockIdx.z;
    const int b = bh >> 4, h = bh & 15;
    const int bm = blockIdx.y * 64, bn = blockIdx.x * 64;
    __shared__ __align__(16) float As[16][68];
    __shared__ __align__(16) float Bs[16][68];
    const int tid = threadIdx.x;
    const int lk = tid & 15, lr = tid >> 4;
    const int tx = tid & 15, ty = tid >> 4;
    float acc[4][4] = {};
    for (int k0 = 0; k0 < DH; k0 += 16) {
        #pragma unroll
        for (int p = 0; p < 4; p++) {
            int m = bm + lr + 16*p;
            As[lk][lr+16*p] = q[((size_t)(b*T_ + m))*D_ + h*DH + k0 + lk];
        }
        #pragma unroll
        for (int p = 0; p < 4; p++) {
            int n = bn + lr + 16*p;
            Bs[lk][lr+16*p] = kmat[((size_t)(b*T_ + n))*D_ + h*DH + k0 + lk];
        }
        __syncthreads();
        #pragma unroll
        for (int k = 0; k < 16; k++) {
            float a[4], bb[4];
            *(float4*)a  = *(const float4*)&As[k][ty*4];
            *(float4*)bb = *(const float4*)&Bs[k][tx*4];
            #pragma unroll
            for (int i = 0; i < 4; i++)
                #pragma unroll
                for (int j = 0; j < 4; j++)
                    acc[i][j] += a[i]*bb[j];
        }
        __syncthreads();
    }
    #pragma unroll
    for (int i = 0; i < 4; i++) {
        int m = bm + ty*4 + i;
        #pragma unroll
        for (int j = 0; j < 4; j++) {
            int n = bn + tx*4 + j;
            s[((size_t)bh*T_ + m)*T_ + n] = acc[i][j] * 0.125f;
        }
    }
}

// Row softmax over 256 entries. One warp per row.
__global__ __launch_bounds__(256)
void softmax_kernel(float* __restrict__ s)
{
    int row  = (blockIdx.x * blockDim.x + threadIdx.x) >> 5;
    int lane = threadIdx.x & 31;
    float* p = s + (size_t)row * T_;
    float v[8];
    float m = -1e30f;
    #pragma unroll
    for (int r = 0; r < 8; r++) { v[r] = p[lane + 32*r]; m = fmaxf(m, v[r]); }
    #pragma unroll
    for (int o = 16; o; o >>= 1) m = fmaxf(m, __shfl_xor_sync(0xffffffffu, m, o));
    float sum = 0.f;
    #pragma unroll
    for (int r = 0; r < 8; r++) { v[r] = __expf(v[r] - m); sum += v[r]; }
    #pragma unroll
    for (int o = 16; o; o >>= 1) sum += __shfl_xor_sync(0xffffffffu, sum, o);
    float inv = 1.f / sum;
    #pragma unroll
    for (int r = 0; r < 8; r++) p[lane + 32*r] = v[r] * inv;
}

// ctx[b,m,h,d] = sum_k P[bh,m,k] v[b,k,h,d]   (BN = 64 = full head dim)
__global__ __launch_bounds__(256)
void attn_ctx_kernel(const float* __restrict__ s, const float* __restrict__ v,
                     float* __restrict__ ctx)
{
    const int bh = blockIdx.z;
    const int b = bh >> 4, h = bh & 15;
    const int bm = blockIdx.y * 64;
    __shared__ __align__(16) float As[16][68];
    __shared__ __align__(16) float Bs[16][68];
    const int tid = threadIdx.x;
    const int lk = tid & 15, lr = tid >> 4;
    const int bn_ = tid & 63, bkk = tid >> 6;
    const int tx = tid & 15, ty = tid >> 4;
    float acc[4][4] = {};
    for (int k0 = 0; k0 < T_; k0 += 16) {
        #pragma unroll
        for (int p = 0; p < 4; p++) {
            int m = bm + lr + 16*p;
            As[lk][lr+16*p] = s[((size_t)bh*T_ + m)*T_ + k0 + lk];
        }
        #pragma unroll
        for (int p = 0; p < 4; p++) {
            int jj = bkk + 4*p;
            Bs[jj][bn_] = v[((size_t)(b*T_ + k0 + jj))*D_ + h*DH + bn_];
        }
        __syncthreads();
        #pragma unroll
        for (int k = 0; k < 16; k++) {
            float a[4], bb[4];
            *(float4*)a  = *(const float4*)&As[k][ty*4];
            *(float4*)bb = *(const float4*)&Bs[k][tx*4];
            #pragma unroll
            for (int i = 0; i < 4; i++)
                #pragma unroll
                for (int j = 0; j < 4; j++)
                    acc[i][j] += a[i]*bb[j];
        }
        __syncthreads();
    }
    #pragma unroll
    for (int i = 0; i < 4; i++) {
        int m = bm + ty*4 + i;
        #pragma unroll
        for (int j = 0; j < 4; j++)
            ctx[((size_t)(b*T_ + m))*D_ + h*DH + tx*4 + j] = acc[i][j];
    }
}

// =====================================================================
// GAT: e1/e2 per (node, head); one warp each.
// =====================================================================
__global__ __launch_bounds__(256)
void e12_kernel(const float* __restrict__ hg, const float* __restrict__ a1,
                const float* __restrict__ a2, float* __restrict__ e1,
                float* __restrict__ e2)
{
    int wid  = (blockIdx.x * blockDim.x + threadIdx.x) >> 5;
    int lane = threadIdx.x & 31;
    int n = wid >> 3, h = wid & 7;
    const float* row = hg + (size_t)n * D_ + h * GDH;
    float s1 = 0.f, s2 = 0.f;
    #pragma unroll
    for (int r = 0; r < 4; r++) {
        float x = row[lane + 32*r];
        s1 += x * a1[lane + 32*r];
        s2 += x * a2[lane + 32*r];
    }
    #pragma unroll
    for (int o = 16; o; o >>= 1) {
        s1 += __shfl_xor_sync(0xffffffffu, s1, o);
        s2 += __shfl_xor_sync(0xffffffffu, s2, o);
    }
    if (lane == 0) { e1[n*HGAT + h] = s1; e2[n*HGAT + h] = s2; }
}

__global__ __launch_bounds__(256)
void e2max_kernel(const float* __restrict__ e2, float* __restrict__ m2)
{
    int h = blockIdx.x, tid = threadIdx.x;
    float m = -1e30f;
    for (int n = tid; n < M_; n += 256) m = fmaxf(m, e2[n*HGAT + h]);
    __shared__ float sm[256];
    sm[tid] = m; __syncthreads();
    for (int s = 128; s > 0; s >>= 1) {
        if (tid < s) sm[tid] = fmaxf(sm[tid], sm[tid + s]);
        __syncthreads();
    }
    if (tid == 0) m2[h] = sm[0];
}

// =====================================================================
// GAT aggregation GEMM with on-the-fly alpha, fused denom + ELU + residual.
// Block: (head h, 64-row tile) -> 64 x 128 output. 256 thr, 4x8 micro.
// =====================================================================
__global__ __launch_bounds__(256)
void gat_gemm_kernel(const float* __restrict__ hg, const float* __restrict__ e1,
                     const float* __restrict__ e2, const float* __restrict__ m2,
                     const float* __restrict__ feat, float* __restrict__ out)
{
    const int h  = blockIdx.x;
    const int bm = blockIdx.y * 64;
    __shared__ __align__(16) float As[16][68];
    __shared__ __align__(16) float Bs[16][136];
    __shared__ float se1[64], smrow[64];
    const int tid = threadIdx.x;
    if (tid < 64) {
        float v1 = e1[(bm + tid)*HGAT + h];
        float s = v1 + m2[h];
        smrow[tid] = s > 0.f ? s : 0.2f * s;
        se1[tid] = v1;
    }
    __syncthreads();
    const int lk = tid & 15, lr = tid >> 4;
    const int bd = tid & 127, bj = tid >> 7;
    const int tx = tid & 15, ty = tid >> 4;
    float acc[4][8] = {};
    float dacc[4] = {};
    for (int k0 = 0; k0 < M_; k0 += 16) {
        float e2v = e2[(k0 + lk)*HGAT + h];
        #pragma unroll
        for (int p = 0; p < 4; p++) {
            int i = lr + 16*p;
            float s = se1[i] + e2v;
            float l = s > 0.f ? s : 0.2f * s;
            As[lk][i] = __expf(l - smrow[i]);
        }
        #pragma unroll
        for (int p = 0; p < 8; p++) {
            int jj = bj + 2*p;
            Bs[jj][bd] = hg[(size_t)(k0 + jj)*D_ + h*GDH + bd];
        }
        __syncthreads();
        #pragma unroll
        for (int k = 0; k < 16; k++) {
            float a[4], b[8];
            *(float4*)a      = *(const float4*)&As[k][ty*4];
            *(float4*)&b[0]  = *(const float4*)&Bs[k][tx*8];
            *(float4*)&b[4]  = *(const float4*)&Bs[k][tx*8 + 4];
            #pragma unroll
            for (int i = 0; i < 4; i++) {
                dacc[i] += a[i];
                #pragma unroll
                for (int j = 0; j < 8; j++)
                    acc[i][j] += a[i]*b[j];
            }
        }
        __syncthreads();
    }
    #pragma unroll
    for (int i = 0; i < 4; i++) {
        int m = bm + ty*4 + i;
        float inv = 1.f / dacc[i];
        #pragma unroll
        for (int j = 0; j < 8; j++) {
            float v = acc[i][j] * inv;
            v = v > 0.f ? v : expm1f(v);                 // ELU
            int col = h*GDH + tx*8 + j;
            out[(size_t)m*D_ + col] = v + feat[(size_t)m*D_ + col];
        }
    }
}

// =====================================================================
extern "C" void kernel_launch(void* const* d_in, const int* in_sizes, int n_in,
                              void* d_out, int out_size)
{
    const float* feat = (const float*)d_in[0];

    // Bind conv weights/biases by SIZE (robust to interleaved or grouped order).
    const float* cw[5];
    const float* cb[5];
    int wi = 0, bi = 0;
    for (int i = 1; i <= 10; i++) {
        if (in_sizes[i] == D_ * D_ * KW) { if (wi < 5) cw[wi++] = (const float*)d_in[i]; }
        else                             { if (bi < 5) cb[bi++] = (const float*)d_in[i]; }
    }

    const float* fp_w = (const float*)d_in[11];
    const float* fp_b = (const float*)d_in[12];
    const float* ln_g = (const float*)d_in[13];
    const float* ln_b = (const float*)d_in[14];
    const float* wq = (const float*)d_in[15];
    const float* bq = (const float*)d_in[16];
    const float* wk = (const float*)d_in[17];
    const float* bk = (const float*)d_in[18];
    const float* wv = (const float*)d_in[19];
    const float* bv = (const float*)d_in[20];
    const float* wo = (const float*)d_in[21];
    const float* bo = (const float*)d_in[22];
    const float* gat_w = (const float*)d_in[23];
    const float* gat_b = (const float*)d_in[24];
    const float* a1 = (const float*)d_in[25];
    const float* a2 = (const float*)d_in[26];
    float* out = (float*)d_out;

    float *wt, *ms, *z, *q, *k, *v, *s, *ctx, *att, *hg, *e1, *e2, *m2;
    cudaGetSymbolAddress((void**)&wt,  g_wt);
    cudaGetSymbolAddress((void**)&ms,  g_ms);
    cudaGetSymbolAddress((void**)&z,   g_z);
    cudaGetSymbolAddress((void**)&q,   g_q);
    cudaGetSymbolAddress((void**)&k,   g_k);
    cudaGetSymbolAddress((void**)&v,   g_v);
    cudaGetSymbolAddress((void**)&s,   g_s);
    cudaGetSymbolAddress((void**)&ctx, g_ctx);
    cudaGetSymbolAddress((void**)&att, g_att);
    cudaGetSymbolAddress((void**)&hg,  g_hg);
    cudaGetSymbolAddress((void**)&e1,  g_e1);
    cudaGetSymbolAddress((void**)&e2,  g_e2);
    cudaGetSymbolAddress((void**)&m2,  g_m2);

    const int dil[5] = {1, 2, 4, 8, 16};
    const int WTN = KW * D_ * D_;                    // 7,340,032 per conv

    // 0) transform conv weights to [tap][o][ci] (coalesced GEMM loads)
    for (int c = 0; c < 5; c++)
        wtrans_kernel<<<WTN / 256, 256>>>(cw[c], wt + (size_t)c * WTN);

    // 1) dilated convs -> g_ms (2048, 5120)
    for (int c = 0; c < 5; c++)
        conv128_kernel<<<dim3(8, 16), 256>>>(feat, wt + (size_t)c * WTN, cb[c], ms,
                                             dil[c], c*D_);

    // 2) fusion projection (K=5120) -> g_z, then LN+GELU in place
    gemm128_wT<<<dim3(8, 16), 256>>>(ms, fp_w, fp_b, z, K5D, K5D, K5D, D_);
    ln_gelu_kernel<<<M_, 256>>>(z, ln_g, ln_b);

    // 3) q, k, v projections
    gemm128_wT<<<dim3(8, 16), 256>>>(z, wq, bq, q, D_, D_, D_, D_);
    gemm128_wT<<<dim3(8, 16), 256>>>(z, wk, bk, k, D_, D_, D_, D_);
    gemm128_wT<<<dim3(8, 16), 256>>>(z, wv, bv, v, D_, D_, D_, D_);

    // 4) attention
    attn_scores_kernel<<<dim3(4, 4, B_*HMHA), 256>>>(q, k, s);
    softmax_kernel<<<(B_*HMHA*T_)/8, 256>>>(s);
    attn_ctx_kernel<<<dim3(1, 4, B_*HMHA), 256>>>(s, v, ctx);

    // 5) output projection, GAT projection
    gemm128_wT<<<dim3(8, 16), 256>>>(ctx, wo, bo, att, D_, D_, D_, D_);
    gemm128_wT<<<dim3(8, 16), 256>>>(att, gat_w, gat_b, hg, D_, D_, D_, D_);

    // 6) GAT attention logits + stable max
    e12_kernel<<<(M_*HGAT)/8, 256>>>(hg, a1, a2, e1, e2);
    e2max_kernel<<<HGAT, 256>>>(e2, m2);

    // 7) GAT aggregation + ELU + residual -> d_out
    gat_gemm_kernel<<<dim3(HGAT, 32), 256>>>(hg, e1, e2, m2, feat, out);
}